// round 12
// baseline (speedup 1.0000x reference)
#include <cuda_runtime.h>
#include <cuda_bf16.h>
#include <cstdint>

// SimCLR loss, B=4096, D=128, T=0.1.  compute_103-safe.
// FP8 e4m3 mma.sync.m16n8k32 (2x bf16 HMMA rate). Persistent 148-CTA
// schedule over 4096 tiles of 128x128. A register-resident per row-block
// segment; B double-buffered. diag captured from MMA (bit-exact cancel);
// pos computed EXACTLY in fp32 in the norm kernel (fp8 error there would
// dominate the loss otherwise).

#define BDIM 4096
#define N2   8192
#define DDIM 128
#define TOT  4096                // 64 row-blocks x 64 col-tiles
#define GRID 148
#define RSB  144                 // smem row stride bytes (128 fp8 + 16B pad)

#define LOG2E10 14.42695040888963f   // 10/ln2

// ---- scratch (__device__ globals; no cudaMalloc allowed) ----
__device__ uint8_t g_z8[N2 * DDIM];         // 1 MB normalized e4m3 rows
__device__ float g_psum[N2];                // exp row sums (atomic; incl diag)
__device__ float g_diag[N2];                // sim_ii as computed by fp8 MMA
__device__ float g_pos[N2];                 // exact fp32 positives

// ---- helpers ----
__device__ __forceinline__ uint32_t smem_u32(const void* p) {
    uint32_t a;
    asm("{ .reg .u64 t; cvta.to.shared.u64 t, %1; cvt.u32.u64 %0, t; }"
        : "=r"(a) : "l"(p));
    return a;
}
__device__ __forceinline__ float expt(float s) {   // exp(10*s), shared w/ loss
    float e;
    asm("ex2.approx.ftz.f32 %0, %1;" : "=f"(e) : "f"(s * LOG2E10));
    return e;
}
// pack 4 floats -> 4 e4m3 bytes (v0 in lowest byte)
__device__ __forceinline__ uint32_t fp8x4(float v0, float v1, float v2, float v3) {
    unsigned short p01, p23;
    asm("cvt.rn.satfinite.e4m3x2.f32 %0, %1, %2;" : "=h"(p01) : "f"(v1), "f"(v0));
    asm("cvt.rn.satfinite.e4m3x2.f32 %0, %1, %2;" : "=h"(p23) : "f"(v3), "f"(v2));
    return (uint32_t)p01 | ((uint32_t)p23 << 16);
}

#define CPA16(dst, src) \
    asm volatile("cp.async.cg.shared.global [%0], [%1], 16;" \
                 :: "r"(dst), "l"(src) : "memory")
#define CPA_COMMIT() asm volatile("cp.async.commit_group;" ::: "memory")
#define CPA_WAIT0()  asm volatile("cp.async.wait_group 0;" ::: "memory")

#define LDSM4(r0, r1, r2, r3, a) \
    asm volatile("ldmatrix.sync.aligned.m8n8.x4.shared.b16 {%0,%1,%2,%3}, [%4];" \
                 : "=r"(r0), "=r"(r1), "=r"(r2), "=r"(r3) : "r"(a))

__device__ __forceinline__ void mmafp8(float* d, const uint32_t* a,
                                       uint32_t b0, uint32_t b1) {
    asm volatile(
        "mma.sync.aligned.m16n8k32.row.col.f32.e4m3.e4m3.f32 "
        "{%0,%1,%2,%3}, {%4,%5,%6,%7}, {%8,%9}, {%0,%1,%2,%3};"
        : "+f"(d[0]), "+f"(d[1]), "+f"(d[2]), "+f"(d[3])
        : "r"(a[0]), "r"(a[1]), "r"(a[2]), "r"(a[3]), "r"(b0), "r"(b1));
}

// ---- SMEM: A block + two B buffers, 128 rows x 144B each ----
#define BLKB  18432
#define SM_A   0
#define SM_B0  BLKB
#define SM_B1  (2 * BLKB)
#define SM_TOTAL (3 * BLKB)      // 55296

__device__ __forceinline__ void load_blk(uint32_t dst, int blk, int tid) {
    #pragma unroll
    for (int i = 0; i < 4; i++) {           // 1024 16B chunks / 256 thr
        int idx = tid + i * 256;
        int r = idx >> 3, c = idx & 7;
        CPA16(dst + r * RSB + c * 16,
              g_z8 + (size_t)(blk * 128 + r) * DDIM + c * 16);
    }
}

// ---------------------------------------------------------------------------
// Kernel 1: normalize pair rows -> e4m3, exact fp32 positives, zero psum.
// One warp per pair r (<4096): handles z rows r and r+4096 and pos.
// ---------------------------------------------------------------------------
__global__ void norm_kernel(const float* __restrict__ xi,
                            const float* __restrict__ xj) {
    int gt = blockIdx.x * blockDim.x + threadIdx.x;
    if (gt < N2) g_psum[gt] = 0.f;

    int pr   = blockIdx.x * 8 + (threadIdx.x >> 5);   // 0..4095
    int lane = threadIdx.x & 31;
    float4 vi = reinterpret_cast<const float4*>(xi + (size_t)pr * DDIM)[lane];
    float4 vj = reinterpret_cast<const float4*>(xj + (size_t)pr * DDIM)[lane];
    float si = vi.x * vi.x + vi.y * vi.y + vi.z * vi.z + vi.w * vi.w;
    float sj = vj.x * vj.x + vj.y * vj.y + vj.z * vj.z + vj.w * vj.w;
    float sd = vi.x * vj.x + vi.y * vj.y + vi.z * vj.z + vi.w * vj.w;
    #pragma unroll
    for (int o = 16; o > 0; o >>= 1) {
        si += __shfl_xor_sync(0xFFFFFFFFu, si, o);
        sj += __shfl_xor_sync(0xFFFFFFFFu, sj, o);
        sd += __shfl_xor_sync(0xFFFFFFFFu, sd, o);
    }
    float invi = 1.0f / fmaxf(sqrtf(si), 1e-12f);
    float invj = 1.0f / fmaxf(sqrtf(sj), 1e-12f);

    *reinterpret_cast<uint32_t*>(g_z8 + (size_t)pr * DDIM + lane * 4) =
        fp8x4(vi.x * invi, vi.y * invi, vi.z * invi, vi.w * invi);
    *reinterpret_cast<uint32_t*>(g_z8 + (size_t)(pr + BDIM) * DDIM + lane * 4) =
        fp8x4(vj.x * invj, vj.y * invj, vj.z * invj, vj.w * invj);

    if (lane == 0) {
        float pos = sd * invi * invj;       // exact fp32 positive
        g_pos[pr] = pos;
        g_pos[pr + BDIM] = pos;
    }
}

// ---------------------------------------------------------------------------
// Kernel 2: persistent FP8 MMA GEMM + fused exp row-sum epilogue.
// 148 CTAs; CTA p handles tiles [p*4096/148, (p+1)*4096/148), rb-major.
// 8 warps = 4 row-warps x 2 col-warps; warp tile 32x64, 2 half-passes of
// 32 cols so ex2 (MUFU) overlaps next half's MMA.
// ---------------------------------------------------------------------------
__global__ void __launch_bounds__(256, 1) simgemm_kernel() {
    extern __shared__ char smem[];
    const uint32_t sb = smem_u32(smem);
    const int tid  = threadIdx.x;
    const int lane = tid & 31;
    const int w    = tid >> 5;
    const int wr   = w & 3;
    const int wc   = w >> 2;

    const int rrow  = (lane & 7) + ((lane >> 3) & 1) * 8;
    const int csel  = lane >> 4;
    const int rquad = lane >> 2;
    const int cpair = (lane & 3) * 2;

    const int t0 = (int)(((long)blockIdx.x * TOT) / GRID);
    const int t1 = (int)(((long)(blockIdx.x + 1) * TOT) / GRID);

    int rb = t0 >> 6;
    load_blk(sb + SM_A, rb, tid);
    load_blk(sb + ((t0 & 1) ? SM_B1 : SM_B0), t0 & 63, tid);
    CPA_COMMIT();
    CPA_WAIT0();
    __syncthreads();

    uint32_t af[4][2][4];
    bool need_af = true;
    float rsum[4] = {0.f, 0.f, 0.f, 0.f};

    for (int t = t0; t < t1; t++) {
        const int ct = t & 63;

        bool fresh_af = false;
        if (need_af) {          // A fragments for this row-block (registers)
            #pragma unroll
            for (int ks = 0; ks < 4; ks++)
                #pragma unroll
                for (int i = 0; i < 2; i++) {
                    uint32_t a = sb + SM_A + (wr * 32 + i * 16 + rrow) * RSB
                               + (ks * 2 + csel) * 16;
                    LDSM4(af[ks][i][0], af[ks][i][1], af[ks][i][2], af[ks][i][3], a);
                }
            need_af = false;
            fresh_af = true;
        }

        // prefetch B(t+1) (and A of next row-block at segment boundary)
        if (t + 1 < t1) {
            const bool prefA = ((t + 1) >> 6) != rb;
            if (prefA && fresh_af) __syncthreads();   // race guard
            load_blk(sb + (((t + 1) & 1) ? SM_B1 : SM_B0), (t + 1) & 63, tid);
            if (prefA) load_blk(sb + SM_A, (t + 1) >> 6, tid);
            CPA_COMMIT();
        }

        const uint32_t sbB = sb + ((t & 1) ? SM_B1 : SM_B0);
        const bool isdiag = (ct == rb);

        // ---- two half-passes of 32 cols: MMA then exp, overlapped ----
        #pragma unroll
        for (int gp = 0; gp < 2; gp++) {
            uint32_t bfp[4][2][4];
            #pragma unroll
            for (int ks = 0; ks < 4; ks++)
                #pragma unroll
                for (int gs = 0; gs < 2; gs++) {
                    uint32_t a = sbB + (wc * 64 + gp * 32 + gs * 16 + rrow) * RSB
                               + (ks * 2 + csel) * 16;
                    LDSM4(bfp[ks][gs][0], bfp[ks][gs][1],
                          bfp[ks][gs][2], bfp[ks][gs][3], a);
                }
            float accp[2][4][4];
            #pragma unroll
            for (int i = 0; i < 2; i++)
                #pragma unroll
                for (int j = 0; j < 4; j++)
                    #pragma unroll
                    for (int c = 0; c < 4; c++) accp[i][j][c] = 0.f;
            #pragma unroll
            for (int ks = 0; ks < 4; ks++)
                #pragma unroll
                for (int i = 0; i < 2; i++)
                    #pragma unroll
                    for (int j = 0; j < 4; j++)
                        mmafp8(accp[i][j], af[ks][i],
                               bfp[ks][j >> 1][j & 1],
                               bfp[ks][j >> 1][(j & 1) + 2]);

            if (isdiag) {       // capture raw sim_ii (bit-exact cancel later)
                #pragma unroll
                for (int i = 0; i < 2; i++)
                    #pragma unroll
                    for (int j = 0; j < 4; j++)
                        #pragma unroll
                        for (int c = 0; c < 4; c++) {
                            int rl = wr * 32 + i * 16 + (c >> 1) * 8 + rquad;
                            int cl = wc * 64 + gp * 32 + j * 8 + cpair + (c & 1);
                            if (cl == rl) g_diag[rb * 128 + rl] = accp[i][j][c];
                        }
            }

            #pragma unroll
            for (int i = 0; i < 2; i++)
                #pragma unroll
                for (int j = 0; j < 4; j++)
                    #pragma unroll
                    for (int c = 0; c < 4; c++)
                        rsum[i * 2 + (c >> 1)] += expt(accp[i][j][c]);
        }

        // ---- segment end: flush row sums (atomics, <=2x per CTA) ----
        const bool segend = (t + 1 == t1) || (((t + 1) >> 6) != rb);
        if (segend) {
            #pragma unroll
            for (int qq = 0; qq < 4; qq++) {
                rsum[qq] += __shfl_xor_sync(0xFFFFFFFFu, rsum[qq], 1);
                rsum[qq] += __shfl_xor_sync(0xFFFFFFFFu, rsum[qq], 2);
            }
            if ((lane & 3) == 0) {
                #pragma unroll
                for (int qq = 0; qq < 4; qq++) {
                    int rl = wr * 32 + (qq >> 1) * 16 + (qq & 1) * 8 + rquad;
                    atomicAdd(&g_psum[rb * 128 + rl], rsum[qq]);
                }
            }
            #pragma unroll
            for (int qq = 0; qq < 4; qq++) rsum[qq] = 0.f;
        }

        if (t + 1 < t1) {
            CPA_WAIT0();
            __syncthreads();
            if (((t + 1) >> 6) != rb) { rb = (t + 1) >> 6; need_af = true; }
        }
    }
}

// ---------------------------------------------------------------------------
// Kernel 3: final scalar reduction.
// ---------------------------------------------------------------------------
__global__ void loss_kernel(float* __restrict__ out) {
    __shared__ float sred[1024];
    float s = 0.f;
    for (int r = threadIdx.x; r < N2; r += 1024) {
        float denom = g_psum[r] - expt(g_diag[r]);
        s += logf(denom) - g_pos[r] * 10.0f;
    }
    sred[threadIdx.x] = s;
    __syncthreads();
    for (int o = 512; o > 0; o >>= 1) {
        if (threadIdx.x < o) sred[threadIdx.x] += sred[threadIdx.x + o];
        __syncthreads();
    }
    if (threadIdx.x == 0) out[0] = sred[0] / (float)N2;
}

// ---------------------------------------------------------------------------
extern "C" void kernel_launch(void* const* d_in, const int* in_sizes, int n_in,
                              void* d_out, int out_size) {
    const float* xi = (const float*)d_in[0];
    const float* xj = (const float*)d_in[1];
    float* out = (float*)d_out;

    cudaFuncSetAttribute(simgemm_kernel,
                         cudaFuncAttributeMaxDynamicSharedMemorySize, SM_TOTAL);

    norm_kernel<<<BDIM / 8, 256>>>(xi, xj);
    simgemm_kernel<<<GRID, 256, SM_TOTAL>>>();
    loss_kernel<<<1, 1024>>>(out);
}

// round 15
// speedup vs baseline: 1.1362x; 1.1362x over previous
#include <cuda_runtime.h>
#include <cuda_bf16.h>
#include <cstdint>

// SimCLR loss, B=4096, D=128, T=0.1.  compute_103-safe.
// FP8 e4m3 mma.sync.m16n8k32, SYMMETRIC upper-tri tiles (2080 of 4096),
// I-major so A stays register-resident per segment. z prescaled by
// sqrt(10/ln2) so MMA outputs 14.4269*sim and exp == bare ex2.approx.
// Off-diag tile (I,J): exp row-sums -> block I rows, exp col-sums ->
// block J rows (sim symmetric). diag captured raw (bit-exact cancel);
// pos computed exactly in fp32 in the norm kernel.

#define BDIM 4096
#define N2   8192
#define DDIM 128
#define NBLK 64
#define NPAIRS 2080              // 64*65/2
#define GRID 148
#define RSB  144                 // smem row stride bytes (128 fp8 + 16B pad)

#define SCL 3.798282f            // sqrt(10/ln2); SCL^2 = 14.426950 ~ 10/ln2

// ---- scratch (__device__ globals; no cudaMalloc allowed) ----
__device__ uint8_t g_z8[N2 * DDIM];         // 1 MB normalized+scaled e4m3
__device__ float g_psum[N2];                // exp row sums (atomic; incl diag)
__device__ float g_diag[N2];                // scaled sim_ii from fp8 MMA
__device__ float g_pos[N2];                 // exact fp32 positives

// ---- helpers ----
__device__ __forceinline__ uint32_t smem_u32(const void* p) {
    uint32_t a;
    asm("{ .reg .u64 t; cvta.to.shared.u64 t, %1; cvt.u32.u64 %0, t; }"
        : "=r"(a) : "l"(p));
    return a;
}
__device__ __forceinline__ float exp2a(float s) {  // 2^s (acc is pre-scaled)
    float e;
    asm("ex2.approx.ftz.f32 %0, %1;" : "=f"(e) : "f"(s));
    return e;
}
// pack 4 floats -> 4 e4m3 bytes (v0 in lowest byte)
__device__ __forceinline__ uint32_t fp8x4(float v0, float v1, float v2, float v3) {
    unsigned short p01, p23;
    asm("cvt.rn.satfinite.e4m3x2.f32 %0, %1, %2;" : "=h"(p01) : "f"(v1), "f"(v0));
    asm("cvt.rn.satfinite.e4m3x2.f32 %0, %1, %2;" : "=h"(p23) : "f"(v3), "f"(v2));
    return (uint32_t)p01 | ((uint32_t)p23 << 16);
}

#define CPA16(dst, src) \
    asm volatile("cp.async.cg.shared.global [%0], [%1], 16;" \
                 :: "r"(dst), "l"(src) : "memory")
#define CPA_COMMIT() asm volatile("cp.async.commit_group;" ::: "memory")
#define CPA_WAIT0()  asm volatile("cp.async.wait_group 0;" ::: "memory")

#define LDSM4(r0, r1, r2, r3, a) \
    asm volatile("ldmatrix.sync.aligned.m8n8.x4.shared.b16 {%0,%1,%2,%3}, [%4];" \
                 : "=r"(r0), "=r"(r1), "=r"(r2), "=r"(r3) : "r"(a))

__device__ __forceinline__ void mmafp8(float* d, const uint32_t* a,
                                       uint32_t b0, uint32_t b1) {
    asm volatile(
        "mma.sync.aligned.m16n8k32.row.col.f32.e4m3.e4m3.f32 "
        "{%0,%1,%2,%3}, {%4,%5,%6,%7}, {%8,%9}, {%0,%1,%2,%3};"
        : "+f"(d[0]), "+f"(d[1]), "+f"(d[2]), "+f"(d[3])
        : "r"(a[0]), "r"(a[1]), "r"(a[2]), "r"(a[3]), "r"(b0), "r"(b1));
}

// ---- SMEM: A block + two B buffers, 128 rows x 144B each ----
#define BLKB  18432
#define SM_A   0
#define SM_B0  BLKB
#define SM_B1  (2 * BLKB)
#define SM_TOTAL (3 * BLKB)      // 55296

__device__ __forceinline__ void load_blk(uint32_t dst, int blk, int tid) {
    #pragma unroll
    for (int i = 0; i < 4; i++) {
        int idx = tid + i * 256;
        int r = idx >> 3, c = idx & 7;
        CPA16(dst + r * RSB + c * 16,
              g_z8 + (size_t)(blk * 128 + r) * DDIM + c * 16);
    }
}

__device__ __forceinline__ void map_tile(int t, int& I, int& J) {
    int i = 0, rem = t;
    while (rem >= NBLK - i) { rem -= NBLK - i; ++i; }
    I = i; J = i + rem;
}

// ---------------------------------------------------------------------------
// Kernel 1: normalize pair rows -> scaled e4m3, exact fp32 pos, zero psum.
// ---------------------------------------------------------------------------
__global__ void norm_kernel(const float* __restrict__ xi,
                            const float* __restrict__ xj) {
    int gt = blockIdx.x * blockDim.x + threadIdx.x;
    if (gt < N2) g_psum[gt] = 0.f;

    int pr   = blockIdx.x * 8 + (threadIdx.x >> 5);   // 0..4095
    int lane = threadIdx.x & 31;
    float4 vi = reinterpret_cast<const float4*>(xi + (size_t)pr * DDIM)[lane];
    float4 vj = reinterpret_cast<const float4*>(xj + (size_t)pr * DDIM)[lane];
    float si = vi.x * vi.x + vi.y * vi.y + vi.z * vi.z + vi.w * vi.w;
    float sj = vj.x * vj.x + vj.y * vj.y + vj.z * vj.z + vj.w * vj.w;
    float sd = vi.x * vj.x + vi.y * vj.y + vi.z * vj.z + vi.w * vj.w;
    #pragma unroll
    for (int o = 16; o > 0; o >>= 1) {
        si += __shfl_xor_sync(0xFFFFFFFFu, si, o);
        sj += __shfl_xor_sync(0xFFFFFFFFu, sj, o);
        sd += __shfl_xor_sync(0xFFFFFFFFu, sd, o);
    }
    float invi = SCL / fmaxf(sqrtf(si), 1e-12f);
    float invj = SCL / fmaxf(sqrtf(sj), 1e-12f);

    *reinterpret_cast<uint32_t*>(g_z8 + (size_t)pr * DDIM + lane * 4) =
        fp8x4(vi.x * invi, vi.y * invi, vi.z * invi, vi.w * invi);
    *reinterpret_cast<uint32_t*>(g_z8 + (size_t)(pr + BDIM) * DDIM + lane * 4) =
        fp8x4(vj.x * invj, vj.y * invj, vj.z * invj, vj.w * invj);

    if (lane == 0) {
        float pos = sd * invi * invj / (SCL * SCL);  // exact fp32 positive
        g_pos[pr] = pos;
        g_pos[pr + BDIM] = pos;
    }
}

// ---------------------------------------------------------------------------
// Kernel 2: persistent symmetric FP8 GEMM + fused exp row/col-sum epilogue.
// 148 CTAs; CTA p handles upper-tri tiles [p*2080/148, (p+1)*2080/148),
// I-major. 8 warps = 4 row-warps x 2 col-warps; warp tile 32x64 in 2
// half-passes of 32 cols.
// ---------------------------------------------------------------------------
__global__ void __launch_bounds__(256, 1) simgemm_kernel() {
    extern __shared__ char smem[];
    const uint32_t sb = smem_u32(smem);
    const int tid  = threadIdx.x;
    const int lane = tid & 31;
    const int w    = tid >> 5;
    const int wr   = w & 3;
    const int wc   = w >> 2;

    const int rrow  = (lane & 7) + ((lane >> 3) & 1) * 8;
    const int csel  = lane >> 4;
    const int rquad = lane >> 2;
    const int cpair = (lane & 3) * 2;

    const int t0 = (int)(((long)blockIdx.x * NPAIRS) / GRID);
    const int t1 = (int)(((long)(blockIdx.x + 1) * NPAIRS) / GRID);

    int I, J;
    map_tile(t0, I, J);
    load_blk(sb + SM_A, I, tid);
    load_blk(sb + ((t0 & 1) ? SM_B1 : SM_B0), J, tid);
    CPA_COMMIT();
    CPA_WAIT0();
    __syncthreads();

    uint32_t af[4][2][4];
    bool need_af = true;
    float rsum[4] = {0.f, 0.f, 0.f, 0.f};

    for (int t = t0; t < t1; t++) {
        bool fresh_af = false;
        if (need_af) {          // A fragments for this row-block (registers)
            #pragma unroll
            for (int ks = 0; ks < 4; ks++)
                #pragma unroll
                for (int i = 0; i < 2; i++) {
                    uint32_t a = sb + SM_A + (wr * 32 + i * 16 + rrow) * RSB
                               + (ks * 2 + csel) * 16;
                    LDSM4(af[ks][i][0], af[ks][i][1], af[ks][i][2], af[ks][i][3], a);
                }
            need_af = false;
            fresh_af = true;
        }

        // next tile coordinates (I-major upper-tri)
        int In = I, Jn = J + 1;
        if (Jn == NBLK) { In = I + 1; Jn = In; }
        const bool prefA = (In != I);

        if (t + 1 < t1) {
            if (prefA && fresh_af) __syncthreads();   // race guard
            load_blk(sb + (((t + 1) & 1) ? SM_B1 : SM_B0), Jn, tid);
            if (prefA) load_blk(sb + SM_A, In, tid);
            CPA_COMMIT();
        }

        const uint32_t sbB = sb + ((t & 1) ? SM_B1 : SM_B0);
        const bool isdiag = (J == I);

        // ---- two half-passes of 32 cols ----
        #pragma unroll
        for (int gp = 0; gp < 2; gp++) {
            uint32_t bfp[4][2][4];
            #pragma unroll
            for (int ks = 0; ks < 4; ks++)
                #pragma unroll
                for (int gs = 0; gs < 2; gs++) {
                    uint32_t a = sbB + (wc * 64 + gp * 32 + gs * 16 + rrow) * RSB
                               + (ks * 2 + csel) * 16;
                    LDSM4(bfp[ks][gs][0], bfp[ks][gs][1],
                          bfp[ks][gs][2], bfp[ks][gs][3], a);
                }
            float accp[2][4][4];
            #pragma unroll
            for (int i = 0; i < 2; i++)
                #pragma unroll
                for (int j = 0; j < 4; j++)
                    #pragma unroll
                    for (int c = 0; c < 4; c++) accp[i][j][c] = 0.f;
            #pragma unroll
            for (int ks = 0; ks < 4; ks++)
                #pragma unroll
                for (int i = 0; i < 2; i++)
                    #pragma unroll
                    for (int j = 0; j < 4; j++)
                        mmafp8(accp[i][j], af[ks][i],
                               bfp[ks][j >> 1][j & 1],
                               bfp[ks][j >> 1][(j & 1) + 2]);

            if (isdiag) {       // capture scaled sim_ii (bit-exact cancel)
                #pragma unroll
                for (int i = 0; i < 2; i++)
                    #pragma unroll
                    for (int j = 0; j < 4; j++)
                        #pragma unroll
                        for (int c = 0; c < 4; c++) {
                            int rl = wr * 32 + i * 16 + (c >> 1) * 8 + rquad;
                            int cl = wc * 64 + gp * 32 + j * 8 + cpair + (c & 1);
                            if (cl == rl) g_diag[I * 128 + rl] = accp[i][j][c];
                        }
            }

            // exp in place (accumulator is pre-scaled: just ex2)
            #pragma unroll
            for (int i = 0; i < 2; i++)
                #pragma unroll
                for (int j = 0; j < 4; j++)
                    #pragma unroll
                    for (int c = 0; c < 4; c++)
                        accp[i][j][c] = exp2a(accp[i][j][c]);

            // row sums -> rows of block I
            #pragma unroll
            for (int i = 0; i < 2; i++)
                #pragma unroll
                for (int j = 0; j < 4; j++)
                    #pragma unroll
                    for (int c = 0; c < 4; c++)
                        rsum[i * 2 + (c >> 1)] += accp[i][j][c];

            // col sums -> rows of block J (off-diagonal tiles only)
            if (!isdiag) {
                #pragma unroll
                for (int j = 0; j < 4; j++)
                    #pragma unroll
                    for (int cc = 0; cc < 2; cc++) {
                        float cs = accp[0][j][cc] + accp[0][j][cc + 2]
                                 + accp[1][j][cc] + accp[1][j][cc + 2];
                        cs += __shfl_xor_sync(0xFFFFFFFFu, cs, 4);
                        cs += __shfl_xor_sync(0xFFFFFFFFu, cs, 8);
                        cs += __shfl_xor_sync(0xFFFFFFFFu, cs, 16);
                        if (lane < 4)
                            atomicAdd(&g_psum[J * 128 + wc * 64 + gp * 32
                                              + j * 8 + (lane & 3) * 2 + cc], cs);
                    }
            }
        }

        // ---- segment end: flush row sums ----
        const bool segend = (t + 1 == t1) || prefA;
        if (segend) {
            #pragma unroll
            for (int qq = 0; qq < 4; qq++) {
                rsum[qq] += __shfl_xor_sync(0xFFFFFFFFu, rsum[qq], 1);
                rsum[qq] += __shfl_xor_sync(0xFFFFFFFFu, rsum[qq], 2);
            }
            if ((lane & 3) == 0) {
                #pragma unroll
                for (int qq = 0; qq < 4; qq++) {
                    int rl = wr * 32 + (qq >> 1) * 16 + (qq & 1) * 8 + rquad;
                    atomicAdd(&g_psum[I * 128 + rl], rsum[qq]);
                }
            }
            #pragma unroll
            for (int qq = 0; qq < 4; qq++) rsum[qq] = 0.f;
        }

        if (t + 1 < t1) {
            CPA_WAIT0();
            __syncthreads();
            if (prefA) need_af = true;
        }
        I = In; J = Jn;
    }
}

// ---------------------------------------------------------------------------
// Kernel 3: final scalar reduction.
// ---------------------------------------------------------------------------
__global__ void loss_kernel(float* __restrict__ out) {
    __shared__ float sred[1024];
    float s = 0.f;
    for (int r = threadIdx.x; r < N2; r += 1024) {
        float denom = g_psum[r] - exp2a(g_diag[r]);
        s += logf(denom) - g_pos[r] * 10.0f;
    }
    sred[threadIdx.x] = s;
    __syncthreads();
    for (int o = 512; o > 0; o >>= 1) {
        if (threadIdx.x < o) sred[threadIdx.x] += sred[threadIdx.x + o];
        __syncthreads();
    }
    if (threadIdx.x == 0) out[0] = sred[0] / (float)N2;
}

// ---------------------------------------------------------------------------
extern "C" void kernel_launch(void* const* d_in, const int* in_sizes, int n_in,
                              void* d_out, int out_size) {
    const float* xi = (const float*)d_in[0];
    const float* xj = (const float*)d_in[1];
    float* out = (float*)d_out;

    cudaFuncSetAttribute(simgemm_kernel,
                         cudaFuncAttributeMaxDynamicSharedMemorySize, SM_TOTAL);

    norm_kernel<<<BDIM / 8, 256>>>(xi, xj);
    simgemm_kernel<<<GRID, 256, SM_TOTAL>>>();
    loss_kernel<<<1, 1024>>>(out);
}